// round 2
// baseline (speedup 1.0000x reference)
#include <cuda_runtime.h>

#define TT 8192
#define H 512
#define NCTA_L 64          // CTAs per layer
#define NTHREADS 256
#define FULLMASK 0xffffffffu

// ---------------- static scratch (no allocations allowed) ----------------
__device__ float g_hist[TT * H];      // layer-0 hidden history (16 MB, stays in L2)
__device__ float g_h2ring[2][H];      // layer-1 h exchange ring (depth 2 is safe: flag
                                      // wait for step s is a full barrier among L1 CTAs)
__device__ float g_hfinal[H];         // final h2 for the MLP head
__device__ unsigned g_prog0[64];      // layer-0 per-CTA progress (monotonic step count)
__device__ unsigned g_prog1[64];      // layer-1 per-CTA progress

// ---------------- helpers ----------------
struct ULL2 { unsigned long long x, y; };

__device__ __forceinline__ ULL2 ldcg2(const float* p) {   // 4 floats as 2 packed f32x2
    ULL2 v;
    asm volatile("ld.global.cg.v2.u64 {%0,%1},[%2];" : "=l"(v.x), "=l"(v.y) : "l"(p));
    return v;
}
__device__ __forceinline__ ULL2 ldg2(const float* p) {
    ULL2 v;
    asm("ld.global.nc.v2.u64 {%0,%1},[%2];" : "=l"(v.x), "=l"(v.y) : "l"(p));
    return v;
}
__device__ __forceinline__ void unpack2(unsigned long long v, float& lo, float& hi) {
    asm("mov.b64 {%0,%1},%2;" : "=f"(lo), "=f"(hi) : "l"(v));
}
// packed fp32x2 FMA: 2 MACs/instr (PTX-only on Blackwell)
__device__ __forceinline__ void fma2(unsigned long long& acc, unsigned long long a, unsigned long long b) {
    asm("fma.rn.f32x2 %0,%1,%2,%0;" : "+l"(acc) : "l"(a), "l"(b));
}
__device__ __forceinline__ unsigned ldacq(const unsigned* p) {
    unsigned v;
    asm volatile("ld.acquire.gpu.u32 %0,[%1];" : "=r"(v) : "l"(p));
    return v;
}
__device__ __forceinline__ void strel(unsigned* p, unsigned v) {
    asm volatile("st.global.relaxed.gpu.u32 [%0],%1;" :: "l"(p), "r"(v));
}
__device__ __forceinline__ float tanhfast(float x) {
    float y; asm("tanh.approx.f32 %0,%1;" : "=f"(y) : "f"(x)); return y;
}
__device__ __forceinline__ float sigfast(float x) { return 0.5f * tanhfast(0.5f * x) + 0.5f; }

// warp-collective: spin until min(prog[0..63]) >= tgt
__device__ __forceinline__ void wait_prog(const unsigned* prog, unsigned tgt) {
    const int l = threadIdx.x & 31;
    for (;;) {
        unsigned a = ldacq(prog + l);
        unsigned b = ldacq(prog + 32 + l);
        if (__all_sync(FULLMASK, (a >= tgt) & (b >= tgt))) return;
    }
}

// ---------------- init: reset progress flags ----------------
__global__ void init_kernel() {
    int t = threadIdx.x;
    if (t < 64) { g_prog0[t] = 0u; g_prog1[t] = 0u; }
}

// ---------------- fused 2-layer persistent LSTM ----------------
// 128 CTAs x 256 threads (1/SM). CTAs [0,64): layer 0; [64,128): layer 1.
// Per CTA: warp wu owns h output j = b*8+wu, i.e. gate rows {j, H+j, 2H+j, 3H+j}.
// Lane l: sec = l>>3 (gate i/f/g/o), cg = l&7 (64-column group).
__global__ void __launch_bounds__(NTHREADS, 1) fused_lstm_kernel(
    const float* __restrict__ x,
    const float* __restrict__ wih0, const float* __restrict__ whh0,
    const float* __restrict__ bih0, const float* __restrict__ bhh0,
    const float* __restrict__ wih1, const float* __restrict__ whh1,
    const float* __restrict__ bih1, const float* __restrict__ bhh1)
{
    const int tid = threadIdx.x;
    const int wu  = tid >> 5;
    const int l   = tid & 31;
    const int cg  = l & 7;
    const bool L1 = blockIdx.x >= NCTA_L;
    const int b   = L1 ? (blockIdx.x - NCTA_L) : blockIdx.x;
    const int j   = b * 8 + wu;
    const int row = (l >> 3) * H + j;          // this lane's gate row
    const int coff = cg * 64;                  // this lane's column offset

    __shared__ float sx[TT];                   // raw input (layer 0 only)
    if (!L1) for (int i = tid; i < TT; i += NTHREADS) sx[i] = x[i];

    // recurrent weights -> registers (64 floats = 32 packed f32x2)
    unsigned long long rw[32];
    {
        const float* p = (L1 ? whh1 : whh0) + (size_t)row * H + coff;
#pragma unroll
        for (int k = 0; k < 16; k++) { ULL2 v = ldg2(p + 4 * k); rw[2*k] = v.x; rw[2*k+1] = v.y; }
    }
    // layer-1 input weights -> registers
    unsigned long long riw[32];
    if (L1) {
        const float* p = wih1 + (size_t)row * H + coff;
#pragma unroll
        for (int k = 0; k < 16; k++) { ULL2 v = ldg2(p + 4 * k); riw[2*k] = v.x; riw[2*k+1] = v.y; }
    }

    const float* bihp = L1 ? bih1 : bih0;
    const float* bhhp = L1 ? bhh1 : bhh0;
    const float bi = bihp[j]       + bhhp[j];
    const float bf = bihp[H + j]   + bhhp[H + j];
    const float bg = bihp[2*H + j] + bhhp[2*H + j];
    const float bo = bihp[3*H + j] + bhhp[3*H + j];
    float wxi = 0.f, wxf = 0.f, wxg = 0.f, wxo = 0.f;   // NC = 1
    if (!L1) { wxi = wih0[j]; wxf = wih0[H + j]; wxg = wih0[2*H + j]; wxo = wih0[3*H + j]; }

    float c = 0.0f;   // cell state, replicated across lanes (consistent: same inputs)
    __syncthreads();

    if (!L1) {
        // ================= layer 0 =================
        for (int t = 0; t < TT; t++) {
            unsigned long long a0 = 0ull, a1 = 0ull;
            if (t > 0) {
                wait_prog(g_prog0, (unsigned)t);
                const float* hb = g_hist + (size_t)(t - 1) * H + coff;
#pragma unroll
                for (int k = 0; k < 16; k++) {
                    ULL2 hv = ldcg2(hb + 4 * k);
                    fma2(a0, rw[2*k],   hv.x);
                    fma2(a1, rw[2*k+1], hv.y);
                }
            }
            float p0, p1, q0, q1;
            unpack2(a0, p0, p1); unpack2(a1, q0, q1);
            float s = (p0 + p1) + (q0 + q1);
            s += __shfl_xor_sync(FULLMASK, s, 1);
            s += __shfl_xor_sync(FULLMASK, s, 2);
            s += __shfl_xor_sync(FULLMASK, s, 4);
            const float xt = sx[t];
            float iv = __shfl_sync(FULLMASK, s, cg)      + bi + wxi * xt;
            float fv = __shfl_sync(FULLMASK, s, 8 + cg)  + bf + wxf * xt;
            float gv = __shfl_sync(FULLMASK, s, 16 + cg) + bg + wxg * xt;
            float ov = __shfl_sync(FULLMASK, s, 24 + cg) + bo + wxo * xt;
            float ii = sigfast(iv), ff = sigfast(fv), gg = tanhfast(gv), oo = sigfast(ov);
            c = ff * c + ii * gg;
            float hn = oo * tanhfast(c);
            if (l == 0) g_hist[(size_t)t * H + j] = hn;
            __syncthreads();
            if (tid == 0) { __threadfence(); strel(g_prog0 + b, (unsigned)(t + 1)); }
        }
    } else {
        // ================= layer 1 =================
        // precompute W_ih . h1[0]
        unsigned long long i0 = 0ull, i1 = 0ull;
        {
            wait_prog(g_prog0, 1u);
            const float* hb = g_hist + coff;
#pragma unroll
            for (int k = 0; k < 16; k++) {
                ULL2 hv = ldcg2(hb + 4 * k);
                fma2(i0, riw[2*k],   hv.x);
                fma2(i1, riw[2*k+1], hv.y);
            }
        }
        for (int s = 0; s < TT; s++) {
            unsigned long long a0 = i0, a1 = i1;
            if (s > 0) {
                wait_prog(g_prog1, (unsigned)s);
                const float* hb = g_h2ring[(s - 1) & 1] + coff;
#pragma unroll
                for (int k = 0; k < 16; k++) {
                    ULL2 hv = ldcg2(hb + 4 * k);
                    fma2(a0, rw[2*k],   hv.x);
                    fma2(a1, rw[2*k+1], hv.y);
                }
            }
            float p0, p1, q0, q1;
            unpack2(a0, p0, p1); unpack2(a1, q0, q1);
            float ss = (p0 + p1) + (q0 + q1);
            ss += __shfl_xor_sync(FULLMASK, ss, 1);
            ss += __shfl_xor_sync(FULLMASK, ss, 2);
            ss += __shfl_xor_sync(FULLMASK, ss, 4);
            float iv = __shfl_sync(FULLMASK, ss, cg)      + bi;
            float fv = __shfl_sync(FULLMASK, ss, 8 + cg)  + bf;
            float gv = __shfl_sync(FULLMASK, ss, 16 + cg) + bg;
            float ov = __shfl_sync(FULLMASK, ss, 24 + cg) + bo;
            float ii = sigfast(iv), ff = sigfast(fv), gg = tanhfast(gv), oo = sigfast(ov);
            c = ff * c + ii * gg;
            float hn = oo * tanhfast(c);
            if (l == 0) {
                g_h2ring[s & 1][j] = hn;
                if (s == TT - 1) g_hfinal[j] = hn;
            }
            __syncthreads();
            if (tid == 0) { __threadfence(); strel(g_prog1 + b, (unsigned)(s + 1)); }
            // precompute next step's W_ih . h1[s+1] (off the critical path: layer 0 runs ahead)
            if (s + 1 < TT) {
                wait_prog(g_prog0, (unsigned)(s + 2));
                const float* hb = g_hist + (size_t)(s + 1) * H + coff;
                i0 = 0ull; i1 = 0ull;
#pragma unroll
                for (int k = 0; k < 16; k++) {
                    ULL2 hv = ldcg2(hb + 4 * k);
                    fma2(i0, riw[2*k],   hv.x);
                    fma2(i1, riw[2*k+1], hv.y);
                }
            }
        }
    }
}

// ---------------- MLP head on final h2 ----------------
__global__ void head_kernel(const float* __restrict__ w1, const float* __restrict__ b1,
                            const float* __restrict__ w2, const float* __restrict__ b2,
                            float* __restrict__ out)
{
    __shared__ float y1[32];
    const int tid = threadIdx.x, w = tid >> 5, l = tid & 31;
    for (int r = w; r < 20; r += 8) {
        float acc = 0.0f;
        for (int k = l; k < H; k += 32) acc += g_hfinal[k] * w1[r * H + k];
#pragma unroll
        for (int off = 16; off; off >>= 1) acc += __shfl_xor_sync(FULLMASK, acc, off);
        if (l == 0) y1[r] = acc + b1[r];
    }
    __syncthreads();
    if (tid == 0) {
        float o = b2[0];
#pragma unroll
        for (int r = 0; r < 20; r++) o += y1[r] * w2[r];
        out[0] = o;
    }
}

extern "C" void kernel_launch(void* const* d_in, const int* in_sizes, int n_in,
                              void* d_out, int out_size)
{
    const float* x    = (const float*)d_in[0];
    const float* wih0 = (const float*)d_in[1];
    const float* whh0 = (const float*)d_in[2];
    const float* bih0 = (const float*)d_in[3];
    const float* bhh0 = (const float*)d_in[4];
    const float* wih1 = (const float*)d_in[5];
    const float* whh1 = (const float*)d_in[6];
    const float* bih1 = (const float*)d_in[7];
    const float* bhh1 = (const float*)d_in[8];
    const float* w1   = (const float*)d_in[9];
    const float* b1   = (const float*)d_in[10];
    const float* w2   = (const float*)d_in[11];
    const float* b2   = (const float*)d_in[12];
    float* out = (float*)d_out;

    init_kernel<<<1, 64>>>();
    fused_lstm_kernel<<<2 * NCTA_L, NTHREADS>>>(x, wih0, whh0, bih0, bhh0,
                                                wih1, whh1, bih1, bhh1);
    head_kernel<<<1, 256>>>(w1, b1, w2, b2, out);
}

// round 3
// speedup vs baseline: 1.4763x; 1.4763x over previous
#include <cuda_runtime.h>

#define TT 8192
#define H 512
#define NCTA_L 64          // CTAs per layer
#define NTHREADS 256
#define PAD 32             // flag padding: 32 uints = 128B line per CTA
#define FULLMASK 0xffffffffu

// ---------------- static scratch (no allocations allowed) ----------------
__device__ float g_hist[TT * H];          // layer-0 hidden history (16 MB)
__device__ float g_h2ring[2][H];          // layer-1 h exchange ring (depth 2: flag wait
                                          // at step s is a full barrier among L1 CTAs)
__device__ float g_hfinal[H];             // final h2 for the MLP head
__device__ unsigned g_prog0[NCTA_L * PAD];  // per-CTA progress, one 128B line each
__device__ unsigned g_prog1[NCTA_L * PAD];

// ---------------- helpers ----------------
struct ULL2 { unsigned long long x, y; };

__device__ __forceinline__ ULL2 ldcg2(const float* p) {   // 4 floats as 2 packed f32x2
    ULL2 v;
    asm volatile("ld.global.cg.v2.u64 {%0,%1},[%2];" : "=l"(v.x), "=l"(v.y) : "l"(p));
    return v;
}
__device__ __forceinline__ ULL2 ldg2(const float* p) {
    ULL2 v;
    asm("ld.global.nc.v2.u64 {%0,%1},[%2];" : "=l"(v.x), "=l"(v.y) : "l"(p));
    return v;
}
__device__ __forceinline__ void unpack2(unsigned long long v, float& lo, float& hi) {
    asm("mov.b64 {%0,%1},%2;" : "=f"(lo), "=f"(hi) : "l"(v));
}
// packed fp32x2 FMA: 2 MACs/instr (PTX-only on Blackwell)
__device__ __forceinline__ void fma2(unsigned long long& acc, unsigned long long a, unsigned long long b) {
    asm("fma.rn.f32x2 %0,%1,%2,%0;" : "+l"(acc) : "l"(a), "l"(b));
}
__device__ __forceinline__ unsigned ldacq(const unsigned* p) {
    unsigned v;
    asm volatile("ld.acquire.gpu.u32 %0,[%1];" : "=r"(v) : "l"(p));
    return v;
}
__device__ __forceinline__ void strel(unsigned* p, unsigned v) {
    asm volatile("st.release.gpu.u32 [%0],%1;" :: "l"(p), "r"(v));
}
__device__ __forceinline__ void stg4(float* p, float4 v) {
    asm volatile("st.global.cg.v4.f32 [%0],{%1,%2,%3,%4};"
                 :: "l"(p), "f"(v.x), "f"(v.y), "f"(v.z), "f"(v.w));
}
__device__ __forceinline__ float tanhfast(float x) {
    float y; asm("tanh.approx.f32 %0,%1;" : "=f"(y) : "f"(x)); return y;
}
__device__ __forceinline__ float sigfast(float x) { return 0.5f * tanhfast(0.5f * x) + 0.5f; }

// WARP-0-ONLY: spin until all 64 per-CTA flags >= tgt (each flag on its own line)
__device__ __forceinline__ void wait64(const unsigned* prog, unsigned tgt) {
    const int l = threadIdx.x & 31;
    const unsigned* p0 = prog + l * PAD;
    const unsigned* p1 = prog + (32 + l) * PAD;
    for (;;) {
        unsigned a = ldacq(p0);
        unsigned b = ldacq(p1);
        if (__all_sync(FULLMASK, (a >= tgt) & (b >= tgt))) return;
    }
}

// ---------------- init: reset progress flags ----------------
__global__ void init_kernel() {
    int t = threadIdx.x;
    for (int i = t; i < NCTA_L * PAD; i += blockDim.x) { g_prog0[i] = 0u; g_prog1[i] = 0u; }
}

// ---------------- fused 2-layer persistent LSTM ----------------
// 128 CTAs x 256 threads (1 CTA/SM at 254 regs). CTAs [0,64): layer 0; [64,128): layer 1.
// Warp wu owns h output j = b*8+wu (gate rows {j, H+j, 2H+j, 3H+j}).
// Lane l: sec = l>>3 (i/f/g/o), cg = l&7 (64-column group).
__global__ void __launch_bounds__(NTHREADS, 1) fused_lstm_kernel(
    const float* __restrict__ x,
    const float* __restrict__ wih0, const float* __restrict__ whh0,
    const float* __restrict__ bih0, const float* __restrict__ bhh0,
    const float* __restrict__ wih1, const float* __restrict__ whh1,
    const float* __restrict__ bih1, const float* __restrict__ bhh1)
{
    const int tid = threadIdx.x;
    const int wu  = tid >> 5;
    const int l   = tid & 31;
    const int cg  = l & 7;
    const bool L1 = blockIdx.x >= NCTA_L;
    const int b   = L1 ? (blockIdx.x - NCTA_L) : blockIdx.x;
    const int j   = b * 8 + wu;
    const int row = (l >> 3) * H + j;          // this lane's gate row
    const int coff = cg * 64;                  // this lane's column offset

    __shared__ float sx[TT];                   // raw input (layer 0 only)
    __shared__ float sh[8];                    // per-warp h staging for coalesced publish
    if (!L1) for (int i = tid; i < TT; i += NTHREADS) sx[i] = x[i];

    // recurrent weights -> registers (64 floats = 32 packed f32x2)
    unsigned long long rw[32];
    {
        const float* p = (L1 ? whh1 : whh0) + (size_t)row * H + coff;
#pragma unroll
        for (int k = 0; k < 16; k++) { ULL2 v = ldg2(p + 4 * k); rw[2*k] = v.x; rw[2*k+1] = v.y; }
    }
    // layer-1 input weights -> registers
    unsigned long long riw[32];
    if (L1) {
        const float* p = wih1 + (size_t)row * H + coff;
#pragma unroll
        for (int k = 0; k < 16; k++) { ULL2 v = ldg2(p + 4 * k); riw[2*k] = v.x; riw[2*k+1] = v.y; }
    }

    const float* bihp = L1 ? bih1 : bih0;
    const float* bhhp = L1 ? bhh1 : bhh0;
    const float bi = bihp[j]       + bhhp[j];
    const float bf = bihp[H + j]   + bhhp[H + j];
    const float bg = bihp[2*H + j] + bhhp[2*H + j];
    const float bo = bihp[3*H + j] + bhhp[3*H + j];
    float wxi = 0.f, wxf = 0.f, wxg = 0.f, wxo = 0.f;   // NC = 1
    if (!L1) { wxi = wih0[j]; wxf = wih0[H + j]; wxg = wih0[2*H + j]; wxo = wih0[3*H + j]; }

    float c = 0.0f;   // cell state (replicated across lanes; identical inputs)
    __syncthreads();

    if (!L1) {
        // ================= layer 0 =================
        for (int t = 0; t < TT; t++) {
            unsigned long long a0 = 0ull, a1 = 0ull;
            if (t > 0) {
                if (wu == 0) wait64(g_prog0, (unsigned)t);   // single-poller
                __syncthreads();
                const float* hb = g_hist + (size_t)(t - 1) * H + coff;
#pragma unroll
                for (int k = 0; k < 16; k++) {
                    ULL2 hv = ldcg2(hb + 4 * k);
                    fma2(a0, rw[2*k],   hv.x);
                    fma2(a1, rw[2*k+1], hv.y);
                }
            }
            float p0, p1, q0, q1;
            unpack2(a0, p0, p1); unpack2(a1, q0, q1);
            float s = (p0 + p1) + (q0 + q1);
            s += __shfl_xor_sync(FULLMASK, s, 1);
            s += __shfl_xor_sync(FULLMASK, s, 2);
            s += __shfl_xor_sync(FULLMASK, s, 4);
            const float xt = sx[t];
            float iv = __shfl_sync(FULLMASK, s, cg)      + bi + wxi * xt;
            float fv = __shfl_sync(FULLMASK, s, 8 + cg)  + bf + wxf * xt;
            float gv = __shfl_sync(FULLMASK, s, 16 + cg) + bg + wxg * xt;
            float ov = __shfl_sync(FULLMASK, s, 24 + cg) + bo + wxo * xt;
            float ii = sigfast(iv), ff = sigfast(fv), gg = tanhfast(gv), oo = sigfast(ov);
            c = ff * c + ii * gg;
            float hn = oo * tanhfast(c);
            if (l == 0) sh[wu] = hn;
            __syncthreads();
            if (wu == 0) {   // coalesced publish: two float4 stores + release flag
                if (l < 2) stg4(g_hist + (size_t)t * H + b * 8 + l * 4,
                                *(float4*)(sh + l * 4));
                __syncwarp();
                if (l == 0) strel(g_prog0 + b * PAD, (unsigned)(t + 1));
            }
        }
    } else {
        // ================= layer 1 =================
        // precompute W_ih . h1[0]
        unsigned long long i0 = 0ull, i1 = 0ull;
        {
            if (wu == 0) wait64(g_prog0, 1u);
            __syncthreads();
            const float* hb = g_hist + coff;
#pragma unroll
            for (int k = 0; k < 16; k++) {
                ULL2 hv = ldcg2(hb + 4 * k);
                fma2(i0, riw[2*k],   hv.x);
                fma2(i1, riw[2*k+1], hv.y);
            }
        }
        for (int s = 0; s < TT; s++) {
            unsigned long long a0 = i0, a1 = i1;
            if (s > 0) {
                if (wu == 0) wait64(g_prog1, (unsigned)s);
                __syncthreads();
                const float* hb = g_h2ring[(s - 1) & 1] + coff;
#pragma unroll
                for (int k = 0; k < 16; k++) {
                    ULL2 hv = ldcg2(hb + 4 * k);
                    fma2(a0, rw[2*k],   hv.x);
                    fma2(a1, rw[2*k+1], hv.y);
                }
            }
            float p0, p1, q0, q1;
            unpack2(a0, p0, p1); unpack2(a1, q0, q1);
            float ss = (p0 + p1) + (q0 + q1);
            ss += __shfl_xor_sync(FULLMASK, ss, 1);
            ss += __shfl_xor_sync(FULLMASK, ss, 2);
            ss += __shfl_xor_sync(FULLMASK, ss, 4);
            float iv = __shfl_sync(FULLMASK, ss, cg)      + bi;
            float fv = __shfl_sync(FULLMASK, ss, 8 + cg)  + bf;
            float gv = __shfl_sync(FULLMASK, ss, 16 + cg) + bg;
            float ov = __shfl_sync(FULLMASK, ss, 24 + cg) + bo;
            float ii = sigfast(iv), ff = sigfast(fv), gg = tanhfast(gv), oo = sigfast(ov);
            c = ff * c + ii * gg;
            float hn = oo * tanhfast(c);
            if (l == 0) sh[wu] = hn;
            __syncthreads();
            if (wu == 0) {
                if (l < 2) {
                    float4 v = *(float4*)(sh + l * 4);
                    stg4(g_h2ring[s & 1] + b * 8 + l * 4, v);
                    if (s == TT - 1) stg4(g_hfinal + b * 8 + l * 4, v);
                }
                __syncwarp();
                if (l == 0) strel(g_prog1 + b * PAD, (unsigned)(s + 1));
            }
            // prefetch W_ih . h1[s+1] (off critical path: layer 0 runs ~1 step ahead)
            if (s + 1 < TT) {
                if (wu == 0) wait64(g_prog0, (unsigned)(s + 2));
                __syncthreads();
                const float* hb = g_hist + (size_t)(s + 1) * H + coff;
                i0 = 0ull; i1 = 0ull;
#pragma unroll
                for (int k = 0; k < 16; k++) {
                    ULL2 hv = ldcg2(hb + 4 * k);
                    fma2(i0, riw[2*k],   hv.x);
                    fma2(i1, riw[2*k+1], hv.y);
                }
            }
        }
    }
}

// ---------------- MLP head on final h2 ----------------
__global__ void head_kernel(const float* __restrict__ w1, const float* __restrict__ b1,
                            const float* __restrict__ w2, const float* __restrict__ b2,
                            float* __restrict__ out)
{
    __shared__ float y1[32];
    const int tid = threadIdx.x, w = tid >> 5, l = tid & 31;
    for (int r = w; r < 20; r += 8) {
        float acc = 0.0f;
        for (int k = l; k < H; k += 32) acc += g_hfinal[k] * w1[r * H + k];
#pragma unroll
        for (int off = 16; off; off >>= 1) acc += __shfl_xor_sync(FULLMASK, acc, off);
        if (l == 0) y1[r] = acc + b1[r];
    }
    __syncthreads();
    if (tid == 0) {
        float o = b2[0];
#pragma unroll
        for (int r = 0; r < 20; r++) o += y1[r] * w2[r];
        out[0] = o;
    }
}

extern "C" void kernel_launch(void* const* d_in, const int* in_sizes, int n_in,
                              void* d_out, int out_size)
{
    const float* x    = (const float*)d_in[0];
    const float* wih0 = (const float*)d_in[1];
    const float* whh0 = (const float*)d_in[2];
    const float* bih0 = (const float*)d_in[3];
    const float* bhh0 = (const float*)d_in[4];
    const float* wih1 = (const float*)d_in[5];
    const float* whh1 = (const float*)d_in[6];
    const float* bih1 = (const float*)d_in[7];
    const float* bhh1 = (const float*)d_in[8];
    const float* w1   = (const float*)d_in[9];
    const float* b1   = (const float*)d_in[10];
    const float* w2   = (const float*)d_in[11];
    const float* b2   = (const float*)d_in[12];
    float* out = (float*)d_out;

    init_kernel<<<1, 256>>>();
    fused_lstm_kernel<<<2 * NCTA_L, NTHREADS>>>(x, wih0, whh0, bih0, bhh0,
                                                wih1, whh1, bih1, bhh1);
    head_kernel<<<1, 256>>>(w1, b1, w2, b2, out);
}